// round 16
// baseline (speedup 1.0000x reference)
#include <cuda_runtime.h>
#include <cuda_fp16.h>
#include <cstdint>
#include <math.h>

#define BATCH 8
#define EE    16384

// ============================ scratch ============================
__device__ float g_S[4194304];            // [8][512][1024]
__device__ float g_pooled[6291456];       // [8][1024][768]
__device__ float g_hin[6297600];          // [8][1025][768] row0 = text vec
__device__ float g_h[2099200];            // [8][1025][256]
__device__ float g_qkv[6297600];          // [8][1025][768] packed q|k|v
__device__ float g_tpv[25600];
__device__ float g_ET[25600];
__device__ float g_Wc[64000];
__device__ float g_bc[50];
__device__ float g_msum[8192];
__device__ int   g_cnt[8 * 1026];
__device__ int   g_off[8 * 1026];
__device__ int   g_cur[8 * 1026];
__device__ int   g_elist[131072];
// fp16 weight tables, transposed to [N][K]
__device__ __half g_Wh[2752512];
#define OFF_W1   0
#define OFF_W2   786432
#define OFF_NTW  1572864
#define OFF_PROJ 2162688
#define OFF_QKV  2359296

// ============================ helpers ============================
__device__ __forceinline__ uint32_t smem_u32(const void* p) {
    uint32_t a;
    asm("{ .reg .u64 t; cvta.to.shared.u64 t, %1; cvt.u32.u64 %0, t; }" : "=r"(a) : "l"(p));
    return a;
}
__device__ __forceinline__ void ldsm_x4(uint32_t (&r)[4], uint32_t addr) {
    asm volatile("ldmatrix.sync.aligned.m8n8.x4.shared.b16 {%0,%1,%2,%3}, [%4];"
                 : "=r"(r[0]), "=r"(r[1]), "=r"(r[2]), "=r"(r[3]) : "r"(addr));
}
__device__ __forceinline__ void mma_f16(float* c, const uint32_t* a, uint32_t b0, uint32_t b1) {
    asm volatile("mma.sync.aligned.m16n8k16.row.col.f32.f16.f16.f32 "
                 "{%0,%1,%2,%3}, {%4,%5,%6,%7}, {%8,%9}, {%0,%1,%2,%3};"
                 : "+f"(c[0]), "+f"(c[1]), "+f"(c[2]), "+f"(c[3])
                 : "r"(a[0]), "r"(a[1]), "r"(a[2]), "r"(a[3]), "r"(b0), "r"(b1));
}
__device__ __forceinline__ void cp16(uint32_t dst, const void* src) {
    asm volatile("cp.async.cg.shared.global [%0], [%1], 16;"
                 :: "r"(dst), "l"(src) : "memory");
}
#define CP_COMMIT() asm volatile("cp.async.commit_group;" ::: "memory")
#define CP_WAIT1()  asm volatile("cp.async.wait_group 1;" ::: "memory")
#define CP_WAIT0()  asm volatile("cp.async.wait_group 0;" ::: "memory")

// ============================ mega_small ============================
__global__ void mega_small(const int* __restrict__ sentence,
                           const float* __restrict__ mask,
                           const float* __restrict__ we,
                           const float* __restrict__ type_table,
                           const float* __restrict__ type_proj_w,
                           const float* __restrict__ edge_type_table,
                           const float* __restrict__ gnn_we,
                           const float* __restrict__ cls_w,
                           const float* __restrict__ cls_b,
                           const float* __restrict__ cls2_w,
                           const float* __restrict__ cls2_b,
                           const float* __restrict__ nm) {
    const int job = blockIdx.y;
    const int blk = blockIdx.x;
    const int t = threadIdx.x;
    if (job == 0) {                       // text encoder, 8 blocks
        if (blk >= 8) return;
        int b = blk;
        __shared__ float sred[256];
        __shared__ float sm[256];
        __shared__ int   sidx[256];
        float mval = mask[b * 256 + t];
        sidx[t] = sentence[b * 256 + t];
        sm[t] = mval;
        sred[t] = mval;
        __syncthreads();
        for (int s = 128; s > 0; s >>= 1) { if (t < s) sred[t] += sred[t + s]; __syncthreads(); }
        float denom = sred[0] + 1e-9f;
        float a0 = 0.f, a1 = 0.f, a2 = 0.f;
        for (int l = 0; l < 256; l++) {
            const float* row = we + (long long)sidx[l] * 768;
            float m = sm[l];
            a0 += row[t] * m; a1 += row[256 + t] * m; a2 += row[512 + t] * m;
        }
        float* o = g_hin + (long long)b * 1025 * 768;
        o[t] = a0 / denom; o[256 + t] = a1 / denom; o[512 + t] = a2 / denom;
    } else if (job >= 1 && job <= 3) {
        const float* A; const float* Bm; float* Cm; int Mv;
        if (job == 1) { A = type_table; Bm = type_proj_w; Cm = g_tpv; Mv = 100; }
        else if (job == 2) { A = edge_type_table; Bm = gnn_we; Cm = g_ET; Mv = 50; }
        else { A = edge_type_table; Bm = gnn_we + 50 * 256; Cm = g_ET + 50 * 256; Mv = 50; }
        int i = blk * 256 + t;
        if (i >= Mv * 256) return;
        int r = i / 256, c = i % 256;
        float s = 0.f;
        for (int kx = 0; kx < 50; kx++) s += A[r * 50 + kx] * Bm[kx * 256 + c];
        Cm[i] = s;
    } else if (job == 4) {
        int i = blk * 256 + t;
        if (i >= 1280 * 50) return;
        int r = i / 50, c = i % 50;
        float s = 0.f;
        for (int kx = 0; kx < 768; kx++) s += cls_w[r * 768 + kx] * cls2_w[c * 768 + kx];
        g_Wc[i] = s;
    } else if (job == 5) {
        if (blk > 0 || t >= 50) return;
        float s = cls2_b[t];
        for (int j = 0; j < 768; j++) s += cls_b[j] * cls2_w[t * 768 + j];
        g_bc[t] = s;
    } else {
        int i = blk * 256 + t;
        if (i >= 8192) return;
        const float* m = nm + (long long)i * 8;
        float s = 0.f;
        #pragma unroll
        for (int q = 0; q < 8; q++) s += m[q];
        g_msum[i] = s;
    }
}

// ============================ mega_prep: transpose + fp16 ============================
struct P10 { const float* p[10]; };
__global__ void mega_prep(P10 srcs) {
    const int Ks[10] = {768, 1024, 768, 768, 256, 256, 256, 256, 256, 256};
    const int Ns[10] = {1024, 768, 768, 256, 256, 256, 256, 256, 256, 256};
    const int Os[10] = {OFF_W1, OFF_W2, OFF_NTW, OFF_PROJ,
                        OFF_QKV, OFF_QKV + 65536, OFF_QKV + 131072,
                        OFF_QKV + 196608, OFF_QKV + 262144, OFF_QKV + 327680};
    int j = blockIdx.y;
    int K = Ks[j], N = Ns[j];
    int i = blockIdx.x * 256 + threadIdx.x;
    if (i >= K * N) return;
    int n = i / K, k = i % K;
    g_Wh[Os[j] + i] = __float2half_rn(srcs.p[j][(long long)k * N + n]);
}

// ============================ kg pooling ============================
__global__ void poolkg_kernel(const int* __restrict__ nodes,
                              const float* __restrict__ nm,
                              const float* __restrict__ etab) {
    int n = blockIdx.x, b = blockIdx.y, t = threadIdx.x;
    const int* idx = nodes + ((long long)b * 1024 + n) * 8;
    const float* m = nm + ((long long)b * 1024 + n) * 8;
    long long base[8]; float mv[8];
    #pragma unroll
    for (int i = 0; i < 8; i++) { base[i] = (long long)idx[i] * 768; mv[i] = m[i]; }
    float* o = g_pooled + ((long long)b * 1024 + n) * 768;
    for (int e = t; e < 768; e += 256) {
        float s = 0.f;
        #pragma unroll
        for (int i = 0; i < 8; i++) s += etab[base[i] + e] * mv[i];
        o[e] = s;
    }
}

// ============================ fp16 HMMA GEMM, ktile 64 ============================
#define LDK    72           // padded row stride in halfs (144 B)
#define ROWBY  144u
#define A_OFF  0u
#define B_OFF  18432u       // 128*144
#define STAGE_B 36864u
#define GSMEM  73728

template<int FUSE>
__global__ __launch_bounds__(512, 1) void gemm_fp(
    const float* __restrict__ A, long long sA,
    const float* __restrict__ gtab, const int* __restrict__ gidx, long long sG,
    const __half* __restrict__ Bh,
    float* __restrict__ C, long long sC,
    int Mr, int Nc, int Kd,
    const float* __restrict__ bias,
    const float* __restrict__ rowScale, long long sRS,
    const float* __restrict__ addTab, const int* __restrict__ aidx, long long sAI,
    int relu, const float* __restrict__ nmask)
{
    extern __shared__ char dsm[];
    const uint32_t sb = smem_u32(dsm);
    const int tid = threadIdx.x;
    const int lane = tid & 31;
    const int wid = tid >> 5;
    const int b = blockIdx.z;
    const int nBase = blockIdx.x * 128;
    const int mBase = blockIdx.y * 128;

    const int lrow = tid >> 2;
    const int q = tid & 3;
    const int arow = mBase + lrow;
    const bool aval = arow < Mr;
    const int arc = aval ? arow : (Mr - 1);
    const float* gA;
    if (gidx) gA = gtab + (long long)gidx[b * sG + arc] * Kd + q * 16;
    else      gA = A + (long long)b * sA + (long long)arc * Kd + q * 16;
    const __half* gB = Bh + (long long)(nBase + lrow) * Kd + q * 16;
    const uint32_t dstoff = (uint32_t)(lrow * ROWBY + q * 32);

    const int wm = (wid & 3) * 32;
    const int wn = (wid >> 2) * 32;
    float acc[2][4][4];
    #pragma unroll
    for (int mt = 0; mt < 2; mt++)
        #pragma unroll
        for (int nt = 0; nt < 4; nt++)
            #pragma unroll
            for (int qq = 0; qq < 4; qq++) acc[mt][nt][qq] = 0.f;

    const uint32_t aRowOff = (uint32_t)((wm + (lane & 15)) * LDK + (lane >> 4) * 8) * 2;
    const uint32_t bRowOff = (uint32_t)((wn + (lane & 7) + (lane >> 4) * 8) * LDK + ((lane >> 3) & 1) * 8) * 2;

    const int nkt = Kd >> 6;
    float4 rA[4];
    #pragma unroll
    for (int i = 0; i < 4; i++) rA[i] = make_float4(0.f, 0.f, 0.f, 0.f);
    if (aval) {
        #pragma unroll
        for (int i = 0; i < 4; i++) rA[i] = *reinterpret_cast<const float4*>(gA + i * 4);
    }
    cp16(sb + B_OFF + dstoff, gB);
    cp16(sb + B_OFF + dstoff + 16, gB + 8);
    CP_COMMIT();

    for (int kt = 0; kt < nkt; kt++) {
        const uint32_t st = sb + (kt & 1) * STAGE_B;
        {
            __half hh[16];
            const float* af = reinterpret_cast<const float*>(rA);
            #pragma unroll
            for (int i = 0; i < 16; i++) hh[i] = __float2half_rn(af[i]);
            *reinterpret_cast<uint4*>(dsm + (st - sb) + A_OFF + dstoff) = *reinterpret_cast<uint4*>(&hh[0]);
            *reinterpret_cast<uint4*>(dsm + (st - sb) + A_OFF + dstoff + 16) = *reinterpret_cast<uint4*>(&hh[8]);
        }
        if (kt + 1 < nkt) {
            const int k0 = (kt + 1) * 64;
            if (aval) {
                #pragma unroll
                for (int i = 0; i < 4; i++) rA[i] = *reinterpret_cast<const float4*>(gA + k0 + i * 4);
            }
            const uint32_t s1 = sb + ((kt + 1) & 1) * STAGE_B;
            cp16(s1 + B_OFF + dstoff, gB + k0);
            cp16(s1 + B_OFF + dstoff + 16, gB + k0 + 8);
            CP_COMMIT();
            CP_WAIT1();
        } else {
            CP_WAIT0();
        }
        __syncthreads();

        const uint32_t uA = st + A_OFF, uB = st + B_OFF;
        #pragma unroll
        for (int ks = 0; ks < 4; ks++) {
            const uint32_t kso = (uint32_t)(ks * 32);
            uint32_t af[2][4];
            #pragma unroll
            for (int mt = 0; mt < 2; mt++) {
                ldsm_x4(af[mt], uA + aRowOff + (uint32_t)(mt * 16 * LDK * 2) + kso);
            }
            #pragma unroll
            for (int nc = 0; nc < 2; nc++) {
                uint32_t bh[4];
                ldsm_x4(bh, uB + bRowOff + (uint32_t)(nc * 16 * LDK * 2) + kso);
                #pragma unroll
                for (int mt = 0; mt < 2; mt++) {
                    #pragma unroll
                    for (int hf = 0; hf < 2; hf++) {
                        mma_f16(acc[mt][nc * 2 + hf], af[mt], bh[hf * 2], bh[hf * 2 + 1]);
                    }
                }
            }
        }
        __syncthreads();
    }

    if (FUSE == 1) {
        const int mgrp = lane >> 2;
        const int cpair = (lane & 3) * 2;
        #pragma unroll
        for (int mt = 0; mt < 2; mt++) {
            #pragma unroll
            for (int ri = 0; ri < 2; ri++) {
                const int row = mBase + wm + mt * 16 + ri * 8 + mgrp;
                const float m = nmask[(long long)b * 8192 + 4096 + row];
                float vals[8];
                #pragma unroll
                for (int nt = 0; nt < 4; nt++) {
                    const int col = nBase + wn + nt * 8 + cpair;
                    vals[nt * 2 + 0] = fmaxf(acc[mt][nt][ri * 2 + 0] + bias[col], 0.f) * m;
                    vals[nt * 2 + 1] = fmaxf(acc[mt][nt][ri * 2 + 1] + bias[col + 1], 0.f) * m;
                }
                #pragma unroll
                for (int s = 4; s < 32; s <<= 1) {
                    #pragma unroll
                    for (int i = 0; i < 8; i++) vals[i] += __shfl_xor_sync(0xffffffffu, vals[i], s);
                }
                if (mgrp == 0) {
                    const int node = (mBase + wm + mt * 16 + ri * 8) >> 3;
                    float* srow = C + (long long)b * sC + (long long)node * Nc + nBase + wn;
                    #pragma unroll
                    for (int nt = 0; nt < 4; nt++) {
                        srow[nt * 8 + cpair] = vals[nt * 2];
                        srow[nt * 8 + cpair + 1] = vals[nt * 2 + 1];
                    }
                }
            }
        }
        return;
    }

    #pragma unroll
    for (int mt = 0; mt < 2; mt++) {
        const int rbase = mBase + wm + mt * 16 + (lane >> 2);
        #pragma unroll
        for (int ri = 0; ri < 2; ri++) {
            const int row = rbase + ri * 8;
            if (row >= Mr) continue;
            float rs = 1.f;
            if (rowScale) rs = rowScale[b * sRS + row];
            const float* addrow = nullptr;
            if (addTab) addrow = addTab + (long long)aidx[b * sAI + row] * Nc;
            float* crow = C + (long long)b * sC + (long long)row * Nc;
            #pragma unroll
            for (int nt = 0; nt < 4; nt++) {
                const int col = nBase + wn + nt * 8 + (lane & 3) * 2;
                float v0 = acc[mt][nt][ri * 2 + 0];
                float v1 = acc[mt][nt][ri * 2 + 1];
                if (bias) { v0 += bias[col] * rs; v1 += bias[col + 1] * rs; }
                if (addrow) { v0 += addrow[col]; v1 += addrow[col + 1]; }
                if (relu) { v0 = fmaxf(v0, 0.f); v1 = fmaxf(v1, 0.f); }
                *reinterpret_cast<float2*>(crow + col) = make_float2(v0, v1);
            }
        }
    }
}

// ============================ CSR build ============================
__global__ void zero_cnt() {
    int i = blockIdx.x * blockDim.x + threadIdx.x;
    if (i < 8 * 1026) g_cnt[i] = 0;
}
__global__ void count_kernel(const int* __restrict__ edges) {
    int i = blockIdx.x * blockDim.x + threadIdx.x;
    if (i >= BATCH * EE) return;
    int b = i / EE, e = i % EE;
    int dst = edges[(long long)b * 2 * EE + EE + e];
    atomicAdd(&g_cnt[b * 1026 + dst], 1);
}
__global__ void scan_kernel() {
    int b = threadIdx.x;
    if (b >= 8) return;
    int acc = 0;
    for (int i = 0; i < 1026; i++) {
        g_off[b * 1026 + i] = acc;
        g_cur[b * 1026 + i] = acc;
        if (i < 1025) acc += g_cnt[b * 1026 + i];
    }
}
__global__ void fill_kernel(const int* __restrict__ edges) {
    int i = blockIdx.x * blockDim.x + threadIdx.x;
    if (i >= BATCH * EE) return;
    int b = i / EE, e = i % EE;
    int dst = edges[(long long)b * 2 * EE + EE + e];
    int pos = atomicAdd(&g_cur[b * 1026 + dst], 1);
    g_elist[b * EE + pos] = e;
}

// ============================ fused GNN attention (single-pass online softmax) ============================
__device__ __forceinline__ unsigned fenc(float f) {
    unsigned u = __float_as_uint(f);
    return (u & 0x80000000u) ? ~u : (u | 0x80000000u);
}
__device__ __forceinline__ float fdec(unsigned e) {
    return (e & 0x80000000u) ? __uint_as_float(e ^ 0x80000000u) : __uint_as_float(~e);
}

__global__ __launch_bounds__(256) void gnn_edge_kernel(
    const float* __restrict__ qkv,
    float* __restrict__ h,
    const int* __restrict__ edges, const int* __restrict__ etyp,
    const float* __restrict__ ET)
{
    const int node = blockIdx.x;
    const int b = blockIdx.y;
    const int tid = threadIdx.x;
    const int lane = tid & 31;
    const int w = tid >> 5;
    __shared__ float qs[256];
    __shared__ unsigned smax[4];
    __shared__ float sden[4];
    __shared__ float sagg[256];
    qs[tid] = qkv[((long long)b * 1025 + node) * 768 + tid];
    sagg[tid] = 0.f;
    if (tid < 4) { smax[tid] = 0u; sden[tid] = 0.f; }
    __syncthreads();
    const int off = g_off[b * 1026 + node];
    const int deg = g_off[b * 1026 + node + 1] - off;
    const int* el = g_elist + b * EE + off;
    const int* srcArr = edges + (long long)b * 2 * EE;

    // per-warp online softmax state
    float mx[4]   = { -1e30f, -1e30f, -1e30f, -1e30f };
    float wsum[4] = { 0.f, 0.f, 0.f, 0.f };
    float vacc[8] = { 0.f, 0.f, 0.f, 0.f, 0.f, 0.f, 0.f, 0.f };

    for (int ei = w; ei < deg; ei += 8) {
        int e = el[ei];
        int src = srcArr[e];
        int et = etyp[(long long)b * EE + e];
        const float* kr = qkv + ((long long)b * 1025 + src) * 768 + 256;
        const float* vr = qkv + ((long long)b * 1025 + src) * 768 + 512;
        const float* er = ET + et * 256;
        float hc[4] = {0.f, 0.f, 0.f, 0.f};
        float vv[8];
        #pragma unroll
        for (int i = 0; i < 8; i++) {
            int d = i * 32 + lane;
            hc[i >> 1] += qs[d] * (kr[d] + er[d]);
            vv[i] = vr[d];
        }
        #pragma unroll
        for (int s = 16; s > 0; s >>= 1) {
            #pragma unroll
            for (int hh = 0; hh < 4; hh++) hc[hh] += __shfl_xor_sync(0xffffffffu, hc[hh], s);
        }
        float ex[4], sc[4];
        #pragma unroll
        for (int hh = 0; hh < 4; hh++) {
            float lg = hc[hh] * 0.125f;
            float mnew = fmaxf(mx[hh], lg);
            sc[hh] = expf(mx[hh] - mnew);      // 0 on first edge (exp(-huge))
            ex[hh] = expf(lg - mnew);
            wsum[hh] = wsum[hh] * sc[hh] + ex[hh];
            mx[hh] = mnew;
        }
        #pragma unroll
        for (int i = 0; i < 8; i++) {
            vacc[i] = vacc[i] * sc[i >> 1] + ex[i >> 1] * vv[i];
        }
    }

    // cross-warp merge
    if (lane == 0 && deg > 0) {
        #pragma unroll
        for (int hh = 0; hh < 4; hh++) atomicMax(&smax[hh], fenc(mx[hh]));
    }
    __syncthreads();
    if (deg > 0) {
        float scw[4];
        #pragma unroll
        for (int hh = 0; hh < 4; hh++) {
            float mxg = fdec(smax[hh]);
            scw[hh] = expf(mx[hh] - mxg);     // warp had no edges: exp(-1e30 - finite) = 0
        }
        if (lane == 0) {
            #pragma unroll
            for (int hh = 0; hh < 4; hh++) atomicAdd(&sden[hh], wsum[hh] * scw[hh]);
        }
        #pragma unroll
        for (int i = 0; i < 8; i++) atomicAdd(&sagg[i * 32 + lane], vacc[i] * scw[i >> 1]);
    }
    __syncthreads();
    float den = sden[tid >> 6] + 1e-9f;
    const long long rowOff = ((long long)b * 1025 + node) * 256;
    h[rowOff + tid] = fmaxf(h[rowOff + tid] + sagg[tid] / den, 0.f);
}

// ============================ final classifier ============================
__global__ void out_kernel(float* __restrict__ out) {
    int c = blockIdx.x, b = blockIdx.y, t = threadIdx.x;
    __shared__ float red[256];
    const float* ctx = g_h + (long long)b * 1025 * 256;
    const float* lab = g_h + ((long long)b * 1025 + 1 + c) * 256;
    const float* txt = g_hin + (long long)b * 1025 * 768;
    float s = 0.f;
    for (int kx = t; kx < 1280; kx += 256) {
        float x;
        if (kx < 256) x = ctx[kx];
        else if (kx < 512) x = lab[kx - 256];
        else x = txt[kx - 512];
        s += x * g_Wc[kx * 50 + c];
    }
    red[t] = s;
    __syncthreads();
    for (int st = 128; st > 0; st >>= 1) { if (t < st) red[t] += red[t + st]; __syncthreads(); }
    if (t == 0) out[b * 50 + c] = red[0] + g_bc[c];
}

// ============================ host ============================
static void launch_g(const float* A, long long sA,
                     const float* gtab, const int* gidx, long long sG,
                     const __half* Bh,
                     float* C, long long sC, int Mr, int Nc, int Kd,
                     const float* bias, const float* rowScale, long long sRS,
                     const float* addTab, const int* aidx, long long sAI, int relu) {
    dim3 grid(Nc / 128, (Mr + 127) / 128, BATCH);
    gemm_fp<0><<<grid, 512, GSMEM>>>(A, sA, gtab, gidx, sG, Bh, C, sC, Mr, Nc, Kd,
                                     bias, rowScale, sRS, addTab, aidx, sAI, relu, nullptr);
}

extern "C" void kernel_launch(void* const* d_in, const int* in_sizes, int n_in,
                              void* d_out, int out_size) {
    (void)in_sizes; (void)n_in; (void)out_size;
    const int*   sentence        = (const int*)d_in[0];
    const float* mask            = (const float*)d_in[1];
    const int*   nodes           = (const int*)d_in[2];
    const float* node_mask       = (const float*)d_in[3];
    const int*   node_types      = (const int*)d_in[4];
    const int*   edges           = (const int*)d_in[5];
    const int*   edge_types      = (const int*)d_in[6];
    const float* word_embed      = (const float*)d_in[7];
    const float* entity_table    = (const float*)d_in[8];
    const float* type_table      = (const float*)d_in[9];
    const float* mlp_w1          = (const float*)d_in[10];
    const float* mlp_b1          = (const float*)d_in[11];
    const float* mlp_w2          = (const float*)d_in[12];
    const float* mlp_b2          = (const float*)d_in[13];
    const float* ntw_w           = (const float*)d_in[14];
    const float* proj_w          = (const float*)d_in[15];
    const float* proj_b          = (const float*)d_in[16];
    const float* type_proj_w     = (const float*)d_in[17];
    const float* edge_type_table = (const float*)d_in[18];
    const float* gnn_wq          = (const float*)d_in[19];
    const float* gnn_wk          = (const float*)d_in[20];
    const float* gnn_wv          = (const float*)d_in[21];
    const float* gnn_we          = (const float*)d_in[22];
    const float* cls_w           = (const float*)d_in[23];
    const float* cls_b           = (const float*)d_in[24];
    const float* cls2_w          = (const float*)d_in[25];
    const float* cls2_b          = (const float*)d_in[26];
    float* out = (float*)d_out;

    // one-time setup (first call is the uncaptured correctness run)
    static cudaStream_t s_b = 0, s_c = 0, s_d = 0;
    static cudaEvent_t ev_root = 0, ev_b = 0, ev_c = 0, ev_d = 0;
    static int inited = 0;
    if (!inited) {
        cudaStreamCreateWithFlags(&s_b, cudaStreamNonBlocking);
        cudaStreamCreateWithFlags(&s_c, cudaStreamNonBlocking);
        cudaStreamCreateWithFlags(&s_d, cudaStreamNonBlocking);
        cudaEventCreateWithFlags(&ev_root, cudaEventDisableTiming);
        cudaEventCreateWithFlags(&ev_b, cudaEventDisableTiming);
        cudaEventCreateWithFlags(&ev_c, cudaEventDisableTiming);
        cudaEventCreateWithFlags(&ev_d, cudaEventDisableTiming);
        cudaFuncSetAttribute(gemm_fp<0>, cudaFuncAttributeMaxDynamicSharedMemorySize, GSMEM);
        cudaFuncSetAttribute(gemm_fp<1>, cudaFuncAttributeMaxDynamicSharedMemorySize, GSMEM);
        inited = 1;
    }

    float *pS, *pPool, *pHin, *pH, *pQKV, *pTpv, *pET, *pMsum;
    __half* pWh;
    cudaGetSymbolAddress((void**)&pS, g_S);
    cudaGetSymbolAddress((void**)&pPool, g_pooled);
    cudaGetSymbolAddress((void**)&pHin, g_hin);
    cudaGetSymbolAddress((void**)&pH, g_h);
    cudaGetSymbolAddress((void**)&pQKV, g_qkv);
    cudaGetSymbolAddress((void**)&pTpv, g_tpv);
    cudaGetSymbolAddress((void**)&pET, g_ET);
    cudaGetSymbolAddress((void**)&pMsum, g_msum);
    cudaGetSymbolAddress((void**)&pWh, g_Wh);

    // fork side streams off the main (captured) stream
    cudaEventRecord(ev_root, 0);
    cudaStreamWaitEvent(s_b, ev_root, 0);
    cudaStreamWaitEvent(s_c, ev_root, 0);
    cudaStreamWaitEvent(s_d, ev_root, 0);

    // main stream: weight prep -> MLP1 (critical path)
    P10 srcs;
    srcs.p[0] = mlp_w1; srcs.p[1] = mlp_w2; srcs.p[2] = ntw_w; srcs.p[3] = proj_w;
    srcs.p[4] = gnn_wq; srcs.p[5] = gnn_wk; srcs.p[6] = gnn_wv;
    srcs.p[7] = gnn_wq + 65536; srcs.p[8] = gnn_wk + 65536; srcs.p[9] = gnn_wv + 65536;
    mega_prep<<<dim3(3072, 10), 256>>>(srcs);

    // side stream B: small fused jobs (text, tpv, ET, Wc, bc, msum)
    mega_small<<<dim3(250, 7), 256, 0, s_b>>>(sentence, mask, word_embed, type_table,
                                              type_proj_w, edge_type_table, gnn_we,
                                              cls_w, cls_b, cls2_w, cls2_b, node_mask);
    cudaEventRecord(ev_b, s_b);
    // side stream C: kg pooling
    poolkg_kernel<<<dim3(512, 8), 256, 0, s_c>>>(nodes, node_mask, entity_table);
    cudaEventRecord(ev_c, s_c);
    // side stream D: CSR build
    zero_cnt<<<(8 * 1026 + 255) / 256, 256, 0, s_d>>>();
    count_kernel<<<(BATCH * EE) / 256, 256, 0, s_d>>>(edges);
    scan_kernel<<<1, 8, 0, s_d>>>();
    fill_kernel<<<(BATCH * EE) / 256, 256, 0, s_d>>>(edges);
    cudaEventRecord(ev_d, s_d);

    // MLP1 fused, A gathered from entity_table -> S fp32
    {
        dim3 grid(1024 / 128, 4096 / 128, BATCH);
        gemm_fp<1><<<grid, 512, GSMEM>>>(nullptr, 0, entity_table, nodes + 4096, 8192,
                                         pWh + OFF_W1, pS, 512LL * 1024,
                                         4096, 1024, 768, mlp_b1, nullptr, 0,
                                         nullptr, nullptr, 0, 0, node_mask);
    }
    // join B (msum, text, tpv, ET, Wc, bc) before MLP2 and everything after
    cudaStreamWaitEvent(0, ev_b, 0);
    // MLP2: S @ W2 + b2*msum -> pooled[512:]
    launch_g(pS, 512LL * 1024, nullptr, nullptr, 0, pWh + OFF_W2,
             pPool + 512 * 768, 1024LL * 768, 512, 768, 1024,
             mlp_b2, pMsum + 512, 1024, nullptr, nullptr, 0, 0);
    // join C (pooled kg-half) before ntw
    cudaStreamWaitEvent(0, ev_c, 0);
    // ntw: pooled @ ntw_w -> hin[1:]
    launch_g(pPool, 1024LL * 768, nullptr, nullptr, 0, pWh + OFF_NTW,
             pHin + 768, 1025LL * 768, 1024, 768, 768,
             nullptr, nullptr, 0, nullptr, nullptr, 0, 0);
    // proj: hin @ proj_w + proj_b + tpv[node_types] -> h
    launch_g(pHin, 1025LL * 768, nullptr, nullptr, 0, pWh + OFF_PROJ,
             pH, 1025LL * 256, 1025, 256, 768,
             proj_b, nullptr, 0, pTpv, node_types, 1025, 0);
    // join D (CSR) before GNN
    cudaStreamWaitEvent(0, ev_d, 0);
    // GNN layers: fused qkv gemm (Nc=768) then single-pass edge kernel
    for (int l = 0; l < 2; l++) {
        launch_g(pH, 1025LL * 256, nullptr, nullptr, 0,
                 pWh + OFF_QKV + l * 196608,
                 pQKV, 1025LL * 768, 1025, 768, 256,
                 nullptr, nullptr, 0, nullptr, nullptr, 0, 0);
        gnn_edge_kernel<<<dim3(1025, 8), 256>>>(pQKV, pH, edges, edge_types,
                                                pET + l * 50 * 256);
    }
    out_kernel<<<dim3(50, 8), 256>>>(out);
}

// round 17
// speedup vs baseline: 1.1022x; 1.1022x over previous
#include <cuda_runtime.h>
#include <cuda_fp16.h>
#include <cstdint>
#include <math.h>

#define BATCH 8
#define EE    16384

// ============================ scratch ============================
__device__ float g_S[4194304];            // [8][512][1024]
__device__ float g_pooled[6291456];       // [8][1024][768] (kg half used)
__device__ float g_hin[6297600];          // [8][1025][768] row0 = text vec
__device__ float g_h[2099200];            // [8][1025][256]
__device__ float g_qkv[6297600];          // [8][1025][768] packed q|k|v
__device__ float g_elog[524288];          // [8][16384][4]
__device__ float g_tpv[25600];            // [100][256]  (type_table@type_proj_w + proj_b)
__device__ float g_ET[25600];
__device__ float g_Wc[64000];
__device__ float g_bc[50];
__device__ float g_msum[8192];
__device__ float g_Wnp[196608];           // fp32 ntw@proj [768][256]
__device__ float g_b2np[256];
__device__ int   g_cnt[8 * 1026];
__device__ int   g_off[8 * 1026];
__device__ int   g_cur[8 * 1026];
__device__ int   g_elist[131072];
// fp16 weight tables, transposed to [N][K]
__device__ __half g_Wh[2752512];
#define OFF_W1    0
#define OFF_W2NP  1572864   // [256][1024] fp16 (reuses old NTW region)
#define OFF_WNP   2162688   // [256][768] fp16 (reuses old PROJ region)
#define OFF_QKV   2359296

// ============================ helpers ============================
__device__ __forceinline__ uint32_t smem_u32(const void* p) {
    uint32_t a;
    asm("{ .reg .u64 t; cvta.to.shared.u64 t, %1; cvt.u32.u64 %0, t; }" : "=r"(a) : "l"(p));
    return a;
}
__device__ __forceinline__ void ldsm_x4(uint32_t (&r)[4], uint32_t addr) {
    asm volatile("ldmatrix.sync.aligned.m8n8.x4.shared.b16 {%0,%1,%2,%3}, [%4];"
                 : "=r"(r[0]), "=r"(r[1]), "=r"(r[2]), "=r"(r[3]) : "r"(addr));
}
__device__ __forceinline__ void mma_f16(float* c, const uint32_t* a, uint32_t b0, uint32_t b1) {
    asm volatile("mma.sync.aligned.m16n8k16.row.col.f32.f16.f16.f32 "
                 "{%0,%1,%2,%3}, {%4,%5,%6,%7}, {%8,%9}, {%0,%1,%2,%3};"
                 : "+f"(c[0]), "+f"(c[1]), "+f"(c[2]), "+f"(c[3])
                 : "r"(a[0]), "r"(a[1]), "r"(a[2]), "r"(a[3]), "r"(b0), "r"(b1));
}
__device__ __forceinline__ void cp16(uint32_t dst, const void* src) {
    asm volatile("cp.async.cg.shared.global [%0], [%1], 16;"
                 :: "r"(dst), "l"(src) : "memory");
}
#define CP_COMMIT() asm volatile("cp.async.commit_group;" ::: "memory")
#define CP_WAIT1()  asm volatile("cp.async.wait_group 1;" ::: "memory")
#define CP_WAIT0()  asm volatile("cp.async.wait_group 0;" ::: "memory")

// ============================ mega_small ============================
__global__ void mega_small(const int* __restrict__ sentence,
                           const float* __restrict__ mask,
                           const float* __restrict__ we,
                           const float* __restrict__ type_table,
                           const float* __restrict__ type_proj_w,
                           const float* __restrict__ edge_type_table,
                           const float* __restrict__ gnn_we,
                           const float* __restrict__ cls_w,
                           const float* __restrict__ cls_b,
                           const float* __restrict__ cls2_w,
                           const float* __restrict__ cls2_b,
                           const float* __restrict__ nm,
                           const float* __restrict__ proj_b) {
    const int job = blockIdx.y;
    const int blk = blockIdx.x;
    const int t = threadIdx.x;
    if (job == 0) {                       // text encoder, 8 blocks
        if (blk >= 8) return;
        int b = blk;
        __shared__ float sred[256];
        __shared__ float sm[256];
        __shared__ int   sidx[256];
        float mval = mask[b * 256 + t];
        sidx[t] = sentence[b * 256 + t];
        sm[t] = mval;
        sred[t] = mval;
        __syncthreads();
        for (int s = 128; s > 0; s >>= 1) { if (t < s) sred[t] += sred[t + s]; __syncthreads(); }
        float denom = sred[0] + 1e-9f;
        float a0 = 0.f, a1 = 0.f, a2 = 0.f;
        for (int l = 0; l < 256; l++) {
            const float* row = we + (long long)sidx[l] * 768;
            float m = sm[l];
            a0 += row[t] * m; a1 += row[256 + t] * m; a2 += row[512 + t] * m;
        }
        float* o = g_hin + (long long)b * 1025 * 768;
        o[t] = a0 / denom; o[256 + t] = a1 / denom; o[512 + t] = a2 / denom;
    } else if (job >= 1 && job <= 3) {
        const float* A; const float* Bm; float* Cm; int Mv; int addpb = 0;
        if (job == 1) { A = type_table; Bm = type_proj_w; Cm = g_tpv; Mv = 100; addpb = 1; }
        else if (job == 2) { A = edge_type_table; Bm = gnn_we; Cm = g_ET; Mv = 50; }
        else { A = edge_type_table; Bm = gnn_we + 50 * 256; Cm = g_ET + 50 * 256; Mv = 50; }
        int i = blk * 256 + t;
        if (i >= Mv * 256) return;
        int r = i / 256, c = i % 256;
        float s = 0.f;
        for (int kx = 0; kx < 50; kx++) s += A[r * 50 + kx] * Bm[kx * 256 + c];
        if (addpb) s += proj_b[c];        // fold proj_b into tpv table
        Cm[i] = s;
    } else if (job == 4) {
        int i = blk * 256 + t;
        if (i >= 1280 * 50) return;
        int r = i / 50, c = i % 50;
        float s = 0.f;
        for (int kx = 0; kx < 768; kx++) s += cls_w[r * 768 + kx] * cls2_w[c * 768 + kx];
        g_Wc[i] = s;
    } else if (job == 5) {
        if (blk > 0 || t >= 50) return;
        float s = cls2_b[t];
        for (int j = 0; j < 768; j++) s += cls_b[j] * cls2_w[t * 768 + j];
        g_bc[t] = s;
    } else {
        int i = blk * 256 + t;
        if (i >= 8192) return;
        const float* m = nm + (long long)i * 8;
        float s = 0.f;
        #pragma unroll
        for (int q = 0; q < 8; q++) s += m[q];
        g_msum[i] = s;
    }
}

// ============================ mega_prep: transpose + fp16 (W1 + qkv only) ============================
struct P7 { const float* p[7]; };
__global__ void mega_prep(P7 srcs) {
    const int Ks[7] = {768, 256, 256, 256, 256, 256, 256};
    const int Ns[7] = {1024, 256, 256, 256, 256, 256, 256};
    const int Os[7] = {OFF_W1,
                       OFF_QKV, OFF_QKV + 65536, OFF_QKV + 131072,
                       OFF_QKV + 196608, OFF_QKV + 262144, OFF_QKV + 327680};
    int j = blockIdx.y;
    int K = Ks[j], N = Ns[j];
    int i = blockIdx.x * 256 + threadIdx.x;
    if (i >= K * N) return;
    int n = i / K, k = i % K;
    g_Wh[Os[j] + i] = __float2half_rn(srcs.p[j][(long long)k * N + n]);
}

// ============================ Wnp = ntw @ proj (fp32 + fp16[N][K]) ============================
__global__ void wnp_kernel(const float* __restrict__ ntw_w, const float* __restrict__ proj_w) {
    const int k = blockIdx.x;   // 768 blocks
    const int t = threadIdx.x;  // 256
    __shared__ float row[768];
    for (int j = t; j < 768; j += 256) row[j] = ntw_w[k * 768 + j];
    __syncthreads();
    float s = 0.f;
    for (int j = 0; j < 768; j++) s += row[j] * proj_w[j * 256 + t];
    g_Wnp[k * 256 + t] = s;
    g_Wh[OFF_WNP + t * 768 + k] = __float2half_rn(s);
}

// ============================ W2np = mlp_w2 @ Wnp ; b2np = mlp_b2 @ Wnp ============================
__global__ void w2np_kernel(const float* __restrict__ mlp_w2, const float* __restrict__ mlp_b2) {
    const int k = blockIdx.x;   // 1025 blocks (last = bias row)
    const int t = threadIdx.x;
    __shared__ float row[768];
    if (k < 1024) {
        for (int j = t; j < 768; j += 256) row[j] = mlp_w2[k * 768 + j];
    } else {
        for (int j = t; j < 768; j += 256) row[j] = mlp_b2[j];
    }
    __syncthreads();
    float s = 0.f;
    for (int j = 0; j < 768; j++) s += row[j] * g_Wnp[j * 256 + t];
    if (k < 1024) g_Wh[OFF_W2NP + t * 1024 + k] = __float2half_rn(s);
    else          g_b2np[t] = s;
}

// ============================ h0: text row of h ============================
__global__ void h0_kernel(const float* __restrict__ proj_w, const int* __restrict__ node_types) {
    const int b = blockIdx.x;
    const int t = threadIdx.x;
    __shared__ float tv[768];
    const float* src = g_hin + (long long)b * 1025 * 768;
    for (int j = t; j < 768; j += 256) tv[j] = src[j];
    __syncthreads();
    float s = 0.f;
    for (int j = 0; j < 768; j++) s += tv[j] * proj_w[j * 256 + t];
    s += g_tpv[node_types[b * 1025] * 256 + t];   // tpv includes proj_b
    g_h[(long long)b * 1025 * 256 + t] = s;
}

// ============================ kg pooling ============================
__global__ void poolkg_kernel(const int* __restrict__ nodes,
                              const float* __restrict__ nm,
                              const float* __restrict__ etab) {
    int n = blockIdx.x, b = blockIdx.y, t = threadIdx.x;
    const int* idx = nodes + ((long long)b * 1024 + n) * 8;
    const float* m = nm + ((long long)b * 1024 + n) * 8;
    long long base[8]; float mv[8];
    #pragma unroll
    for (int i = 0; i < 8; i++) { base[i] = (long long)idx[i] * 768; mv[i] = m[i]; }
    float* o = g_pooled + ((long long)b * 1024 + n) * 768;
    for (int e = t; e < 768; e += 256) {
        float s = 0.f;
        #pragma unroll
        for (int i = 0; i < 8; i++) s += etab[base[i] + e] * mv[i];
        o[e] = s;
    }
}

// ============================ fp16 HMMA GEMM, ktile 64 ============================
#define LDK    72
#define ROWBY  144u
#define A_OFF  0u
#define B_OFF  18432u
#define STAGE_B 36864u
#define GSMEM  73728

template<int FUSE>
__global__ __launch_bounds__(512, 1) void gemm_fp(
    const float* __restrict__ A, long long sA,
    const float* __restrict__ gtab, const int* __restrict__ gidx, long long sG,
    const __half* __restrict__ Bh,
    float* __restrict__ C, long long sC,
    int Mr, int Nc, int Kd,
    const float* __restrict__ bias,
    const float* __restrict__ rowScale, long long sRS,
    const float* __restrict__ addTab, const int* __restrict__ aidx, long long sAI,
    int relu, const float* __restrict__ nmask)
{
    extern __shared__ char dsm[];
    const uint32_t sb = smem_u32(dsm);
    const int tid = threadIdx.x;
    const int lane = tid & 31;
    const int wid = tid >> 5;
    const int b = blockIdx.z;
    const int nBase = blockIdx.x * 128;
    const int mBase = blockIdx.y * 128;

    const int lrow = tid >> 2;
    const int q = tid & 3;
    const int arow = mBase + lrow;
    const bool aval = arow < Mr;
    const int arc = aval ? arow : (Mr - 1);
    const float* gA;
    if (gidx) gA = gtab + (long long)gidx[b * sG + arc] * Kd + q * 16;
    else      gA = A + (long long)b * sA + (long long)arc * Kd + q * 16;
    const __half* gB = Bh + (long long)(nBase + lrow) * Kd + q * 16;
    const uint32_t dstoff = (uint32_t)(lrow * ROWBY + q * 32);

    const int wm = (wid & 3) * 32;
    const int wn = (wid >> 2) * 32;
    float acc[2][4][4];
    #pragma unroll
    for (int mt = 0; mt < 2; mt++)
        #pragma unroll
        for (int nt = 0; nt < 4; nt++)
            #pragma unroll
            for (int qq = 0; qq < 4; qq++) acc[mt][nt][qq] = 0.f;

    const uint32_t aRowOff = (uint32_t)((wm + (lane & 15)) * LDK + (lane >> 4) * 8) * 2;
    const uint32_t bRowOff = (uint32_t)((wn + (lane & 7) + (lane >> 4) * 8) * LDK + ((lane >> 3) & 1) * 8) * 2;

    const int nkt = Kd >> 6;
    float4 rA[4];
    #pragma unroll
    for (int i = 0; i < 4; i++) rA[i] = make_float4(0.f, 0.f, 0.f, 0.f);
    if (aval) {
        #pragma unroll
        for (int i = 0; i < 4; i++) rA[i] = *reinterpret_cast<const float4*>(gA + i * 4);
    }
    cp16(sb + B_OFF + dstoff, gB);
    cp16(sb + B_OFF + dstoff + 16, gB + 8);
    CP_COMMIT();

    for (int kt = 0; kt < nkt; kt++) {
        const uint32_t st = sb + (kt & 1) * STAGE_B;
        {
            __half hh[16];
            const float* af = reinterpret_cast<const float*>(rA);
            #pragma unroll
            for (int i = 0; i < 16; i++) hh[i] = __float2half_rn(af[i]);
            *reinterpret_cast<uint4*>(dsm + (st - sb) + A_OFF + dstoff) = *reinterpret_cast<uint4*>(&hh[0]);
            *reinterpret_cast<uint4*>(dsm + (st - sb) + A_OFF + dstoff + 16) = *reinterpret_cast<uint4*>(&hh[8]);
        }
        if (kt + 1 < nkt) {
            const int k0 = (kt + 1) * 64;
            if (aval) {
                #pragma unroll
                for (int i = 0; i < 4; i++) rA[i] = *reinterpret_cast<const float4*>(gA + k0 + i * 4);
            }
            const uint32_t s1 = sb + ((kt + 1) & 1) * STAGE_B;
            cp16(s1 + B_OFF + dstoff, gB + k0);
            cp16(s1 + B_OFF + dstoff + 16, gB + k0 + 8);
            CP_COMMIT();
            CP_WAIT1();
        } else {
            CP_WAIT0();
        }
        __syncthreads();

        const uint32_t uA = st + A_OFF, uB = st + B_OFF;
        #pragma unroll
        for (int ks = 0; ks < 4; ks++) {
            const uint32_t kso = (uint32_t)(ks * 32);
            uint32_t af[2][4];
            #pragma unroll
            for (int mt = 0; mt < 2; mt++) {
                ldsm_x4(af[mt], uA + aRowOff + (uint32_t)(mt * 16 * LDK * 2) + kso);
            }
            #pragma unroll
            for (int nc = 0; nc < 2; nc++) {
                uint32_t bh[4];
                ldsm_x4(bh, uB + bRowOff + (uint32_t)(nc * 16 * LDK * 2) + kso);
                #pragma unroll
                for (int mt = 0; mt < 2; mt++) {
                    #pragma unroll
                    for (int hf = 0; hf < 2; hf++) {
                        mma_f16(acc[mt][nc * 2 + hf], af[mt], bh[hf * 2], bh[hf * 2 + 1]);
                    }
                }
            }
        }
        __syncthreads();
    }

    if (FUSE == 1) {
        const int mgrp = lane >> 2;
        const int cpair = (lane & 3) * 2;
        #pragma unroll
        for (int mt = 0; mt < 2; mt++) {
            #pragma unroll
            for (int ri = 0; ri < 2; ri++) {
                const int row = mBase + wm + mt * 16 + ri * 8 + mgrp;
                const float m = nmask[(long long)b * 8192 + 4096 + row];
                float vals[8];
                #pragma unroll
                for (int nt = 0; nt < 4; nt++) {
                    const int col = nBase + wn + nt * 8 + cpair;
                    vals[nt * 2 + 0] = fmaxf(acc[mt][nt][ri * 2 + 0] + bias[col], 0.f) * m;
                    vals[nt * 2 + 1] = fmaxf(acc[mt][nt][ri * 2 + 1] + bias[col + 1], 0.f) * m;
                }
                #pragma unroll
                for (int s = 4; s < 32; s <<= 1) {
                    #pragma unroll
                    for (int i = 0; i < 8; i++) vals[i] += __shfl_xor_sync(0xffffffffu, vals[i], s);
                }
                if (mgrp == 0) {
                    const int node = (mBase + wm + mt * 16 + ri * 8) >> 3;
                    float* srow = C + (long long)b * sC + (long long)node * Nc + nBase + wn;
                    #pragma unroll
                    for (int nt = 0; nt < 4; nt++) {
                        srow[nt * 8 + cpair] = vals[nt * 2];
                        srow[nt * 8 + cpair + 1] = vals[nt * 2 + 1];
                    }
                }
            }
        }
        return;
    }

    #pragma unroll
    for (int mt = 0; mt < 2; mt++) {
        const int rbase = mBase + wm + mt * 16 + (lane >> 2);
        #pragma unroll
        for (int ri = 0; ri < 2; ri++) {
            const int row = rbase + ri * 8;
            if (row >= Mr) continue;
            float rs = 1.f;
            if (rowScale) rs = rowScale[b * sRS + row];
            const float* addrow = nullptr;
            if (addTab) addrow = addTab + (long long)aidx[b * sAI + row] * Nc;
            float* crow = C + (long long)b * sC + (long long)row * Nc;
            #pragma unroll
            for (int nt = 0; nt < 4; nt++) {
                const int col = nBase + wn + nt * 8 + (lane & 3) * 2;
                float v0 = acc[mt][nt][ri * 2 + 0];
                float v1 = acc[mt][nt][ri * 2 + 1];
                if (bias) { v0 += bias[col] * rs; v1 += bias[col + 1] * rs; }
                if (addrow) { v0 += addrow[col]; v1 += addrow[col + 1]; }
                if (relu) { v0 = fmaxf(v0, 0.f); v1 = fmaxf(v1, 0.f); }
                *reinterpret_cast<float2*>(crow + col) = make_float2(v0, v1);
            }
        }
    }
}

// ============================ CSR build ============================
__global__ void zero_cnt() {
    int i = blockIdx.x * blockDim.x + threadIdx.x;
    if (i < 8 * 1026) g_cnt[i] = 0;
}
__global__ void count_kernel(const int* __restrict__ edges) {
    int i = blockIdx.x * blockDim.x + threadIdx.x;
    if (i >= BATCH * EE) return;
    int b = i / EE, e = i % EE;
    int dst = edges[(long long)b * 2 * EE + EE + e];
    atomicAdd(&g_cnt[b * 1026 + dst], 1);
}
__global__ void scan_kernel() {
    int b = threadIdx.x;
    if (b >= 8) return;
    int acc = 0;
    for (int i = 0; i < 1026; i++) {
        g_off[b * 1026 + i] = acc;
        g_cur[b * 1026 + i] = acc;
        if (i < 1025) acc += g_cnt[b * 1026 + i];
    }
}
__global__ void fill_kernel(const int* __restrict__ edges) {
    int i = blockIdx.x * blockDim.x + threadIdx.x;
    if (i >= BATCH * EE) return;
    int b = i / EE, e = i % EE;
    int dst = edges[(long long)b * 2 * EE + EE + e];
    int pos = atomicAdd(&g_cur[b * 1026 + dst], 1);
    g_elist[b * EE + pos] = e;
}

// ============================ fused GNN attention (champion two-pass) ============================
__device__ __forceinline__ unsigned fenc(float f) {
    unsigned u = __float_as_uint(f);
    return (u & 0x80000000u) ? ~u : (u | 0x80000000u);
}
__device__ __forceinline__ float fdec(unsigned e) {
    return (e & 0x80000000u) ? __uint_as_float(e ^ 0x80000000u) : __uint_as_float(~e);
}

__global__ __launch_bounds__(256) void gnn_edge_kernel(
    const float* __restrict__ qkv,
    float* __restrict__ h,
    const int* __restrict__ edges, const int* __restrict__ etyp,
    const float* __restrict__ ET)
{
    const int node = blockIdx.x;
    const int b = blockIdx.y;
    const int tid = threadIdx.x;
    const int lane = tid & 31;
    const int w = tid >> 5;
    __shared__ float qs[256];
    __shared__ unsigned smax[4];
    __shared__ float sden[4];
    __shared__ float sagg[256];
    qs[tid] = qkv[((long long)b * 1025 + node) * 768 + tid];
    sagg[tid] = 0.f;
    if (tid < 4) { smax[tid] = 0u; sden[tid] = 0.f; }
    __syncthreads();
    const int off = g_off[b * 1026 + node];
    const int deg = g_off[b * 1026 + node + 1] - off;
    const int* el = g_elist + b * EE + off;
    const int* srcArr = edges + (long long)b * 2 * EE;

    float lmax[4] = { -1e30f, -1e30f, -1e30f, -1e30f };
    for (int ei = w; ei < deg; ei += 8) {
        int e = el[ei];
        int src = srcArr[e];
        int et = etyp[(long long)b * EE + e];
        const float* kr = qkv + ((long long)b * 1025 + src) * 768 + 256;
        const float* er = ET + et * 256;
        float hc[4] = {0.f, 0.f, 0.f, 0.f};
        #pragma unroll
        for (int i = 0; i < 8; i++) {
            int d = i * 32 + lane;
            hc[i >> 1] += qs[d] * (kr[d] + er[d]);
        }
        #pragma unroll
        for (int s = 16; s > 0; s >>= 1) {
            #pragma unroll
            for (int hh = 0; hh < 4; hh++) hc[hh] += __shfl_xor_sync(0xffffffffu, hc[hh], s);
        }
        #pragma unroll
        for (int hh = 0; hh < 4; hh++) {
            float lg = hc[hh] * 0.125f;
            lmax[hh] = fmaxf(lmax[hh], lg);
            hc[hh] = lg;
        }
        if (lane < 4) g_elog[((long long)b * EE + off + ei) * 4 + lane] = hc[lane];
    }
    if (lane == 0 && deg > 0) {
        #pragma unroll
        for (int hh = 0; hh < 4; hh++) atomicMax(&smax[hh], fenc(lmax[hh]));
    }
    __syncthreads();
    float mx[4];
    #pragma unroll
    for (int hh = 0; hh < 4; hh++) mx[hh] = fdec(smax[hh]);

    float vacc[8] = {0.f, 0.f, 0.f, 0.f, 0.f, 0.f, 0.f, 0.f};
    float wsum[4] = {0.f, 0.f, 0.f, 0.f};
    for (int ei = w; ei < deg; ei += 8) {
        int e = el[ei];
        int src = srcArr[e];
        float4 lg = *reinterpret_cast<const float4*>(&g_elog[((long long)b * EE + off + ei) * 4]);
        float ex[4];
        ex[0] = expf(lg.x - mx[0]);
        ex[1] = expf(lg.y - mx[1]);
        ex[2] = expf(lg.z - mx[2]);
        ex[3] = expf(lg.w - mx[3]);
        const float* vr = qkv + ((long long)b * 1025 + src) * 768 + 512;
        #pragma unroll
        for (int i = 0; i < 8; i++) {
            int d = i * 32 + lane;
            vacc[i] += ex[i >> 1] * vr[d];
        }
        if (lane == 0) {
            #pragma unroll
            for (int hh = 0; hh < 4; hh++) wsum[hh] += ex[hh];
        }
    }
    if (lane == 0 && deg > 0) {
        #pragma unroll
        for (int hh = 0; hh < 4; hh++) atomicAdd(&sden[hh], wsum[hh]);
    }
    #pragma unroll
    for (int i = 0; i < 8; i++) atomicAdd(&sagg[i * 32 + lane], vacc[i]);
    __syncthreads();
    float den = sden[tid >> 6] + 1e-9f;
    const long long rowOff = ((long long)b * 1025 + node) * 256;
    h[rowOff + tid] = fmaxf(h[rowOff + tid] + sagg[tid] / den, 0.f);
}

// ============================ final classifier ============================
__global__ void out_kernel(float* __restrict__ out) {
    int c = blockIdx.x, b = blockIdx.y, t = threadIdx.x;
    __shared__ float red[256];
    const float* ctx = g_h + (long long)b * 1025 * 256;
    const float* lab = g_h + ((long long)b * 1025 + 1 + c) * 256;
    const float* txt = g_hin + (long long)b * 1025 * 768;
    float s = 0.f;
    for (int kx = t; kx < 1280; kx += 256) {
        float x;
        if (kx < 256) x = ctx[kx];
        else if (kx < 512) x = lab[kx - 256];
        else x = txt[kx - 512];
        s += x * g_Wc[kx * 50 + c];
    }
    red[t] = s;
    __syncthreads();
    for (int st = 128; st > 0; st >>= 1) { if (t < st) red[t] += red[t + st]; __syncthreads(); }
    if (t == 0) out[b * 50 + c] = red[0] + g_bc[c];
}

// ============================ host ============================
static void launch_g(const float* A, long long sA,
                     const float* gtab, const int* gidx, long long sG,
                     const __half* Bh,
                     float* C, long long sC, int Mr, int Nc, int Kd,
                     const float* bias, const float* rowScale, long long sRS,
                     const float* addTab, const int* aidx, long long sAI, int relu) {
    dim3 grid(Nc / 128, (Mr + 127) / 128, BATCH);
    gemm_fp<0><<<grid, 512, GSMEM>>>(A, sA, gtab, gidx, sG, Bh, C, sC, Mr, Nc, Kd,
                                     bias, rowScale, sRS, addTab, aidx, sAI, relu, nullptr);
}

extern "C" void kernel_launch(void* const* d_in, const int* in_sizes, int n_in,
                              void* d_out, int out_size) {
    (void)in_sizes; (void)n_in; (void)out_size;
    const int*   sentence        = (const int*)d_in[0];
    const float* mask            = (const float*)d_in[1];
    const int*   nodes           = (const int*)d_in[2];
    const float* node_mask       = (const float*)d_in[3];
    const int*   node_types      = (const int*)d_in[4];
    const int*   edges           = (const int*)d_in[5];
    const int*   edge_types      = (const int*)d_in[6];
    const float* word_embed      = (const float*)d_in[7];
    const float* entity_table    = (const float*)d_in[8];
    const float* type_table      = (const float*)d_in[9];
    const float* mlp_w1          = (const float*)d_in[10];
    const float* mlp_b1          = (const float*)d_in[11];
    const float* mlp_w2          = (const float*)d_in[12];
    const float* mlp_b2          = (const float*)d_in[13];
    const float* ntw_w           = (const float*)d_in[14];
    const float* proj_w          = (const float*)d_in[15];
    const float* proj_b          = (const float*)d_in[16];
    const float* type_proj_w     = (const float*)d_in[17];
    const float* edge_type_table = (const float*)d_in[18];
    const float* gnn_wq          = (const float*)d_in[19];
    const float* gnn_wk          = (const float*)d_in[20];
    const float* gnn_wv          = (const float*)d_in[21];
    const float* gnn_we          = (const float*)d_in[22];
    const float* cls_w           = (const float*)d_in[23];
    const float* cls_b           = (const float*)d_in[24];
    const float* cls2_w          = (const float*)d_in[25];
    const float* cls2_b          = (const float*)d_in[26];
    float* out = (float*)d_out;

    // one-time setup (first call is the uncaptured correctness run)
    static cudaStream_t s_b = 0, s_c = 0, s_d = 0;
    static cudaEvent_t ev_root = 0, ev_b = 0, ev_c = 0, ev_d = 0;
    static int inited = 0;
    if (!inited) {
        cudaStreamCreateWithFlags(&s_b, cudaStreamNonBlocking);
        cudaStreamCreateWithFlags(&s_c, cudaStreamNonBlocking);
        cudaStreamCreateWithFlags(&s_d, cudaStreamNonBlocking);
        cudaEventCreateWithFlags(&ev_root, cudaEventDisableTiming);
        cudaEventCreateWithFlags(&ev_b, cudaEventDisableTiming);
        cudaEventCreateWithFlags(&ev_c, cudaEventDisableTiming);
        cudaEventCreateWithFlags(&ev_d, cudaEventDisableTiming);
        cudaFuncSetAttribute(gemm_fp<0>, cudaFuncAttributeMaxDynamicSharedMemorySize, GSMEM);
        cudaFuncSetAttribute(gemm_fp<1>, cudaFuncAttributeMaxDynamicSharedMemorySize, GSMEM);
        inited = 1;
    }

    float *pS, *pPool, *pH, *pQKV, *pTpv, *pET, *pMsum, *pB2np;
    __half* pWh;
    cudaGetSymbolAddress((void**)&pS, g_S);
    cudaGetSymbolAddress((void**)&pPool, g_pooled);
    cudaGetSymbolAddress((void**)&pH, g_h);
    cudaGetSymbolAddress((void**)&pQKV, g_qkv);
    cudaGetSymbolAddress((void**)&pTpv, g_tpv);
    cudaGetSymbolAddress((void**)&pET, g_ET);
    cudaGetSymbolAddress((void**)&pMsum, g_msum);
    cudaGetSymbolAddress((void**)&pB2np, g_b2np);
    cudaGetSymbolAddress((void**)&pWh, g_Wh);

    // fork side streams off the main (captured) stream
    cudaEventRecord(ev_root, 0);
    cudaStreamWaitEvent(s_b, ev_root, 0);
    cudaStreamWaitEvent(s_c, ev_root, 0);
    cudaStreamWaitEvent(s_d, ev_root, 0);

    // main stream: weight prep (W1 + qkv) -> MLP1 (critical path)
    P7 srcs;
    srcs.p[0] = mlp_w1;
    srcs.p[1] = gnn_wq; srcs.p[2] = gnn_wk; srcs.p[3] = gnn_wv;
    srcs.p[4] = gnn_wq + 65536; srcs.p[5] = gnn_wk + 65536; srcs.p[6] = gnn_wv + 65536;
    mega_prep<<<dim3(3072, 7), 256>>>(srcs);

    // side stream B: small fused jobs, then folded-weight precomputes
    mega_small<<<dim3(250, 7), 256, 0, s_b>>>(sentence, mask, word_embed, type_table,
                                              type_proj_w, edge_type_table, gnn_we,
                                              cls_w, cls_b, cls2_w, cls2_b, node_mask, proj_b);
    wnp_kernel<<<768, 256, 0, s_b>>>(ntw_w, proj_w);
    w2np_kernel<<<1025, 256, 0, s_b>>>(mlp_w2, mlp_b2);
    cudaEventRecord(ev_b, s_b);
    // side stream C: kg pooling
    poolkg_kernel<<<dim3(512, 8), 256, 0, s_c>>>(nodes, node_mask, entity_table);
    cudaEventRecord(ev_c, s_c);
    // side stream D: CSR build
    zero_cnt<<<(8 * 1026 + 255) / 256, 256, 0, s_d>>>();
    count_kernel<<<(BATCH * EE) / 256, 256, 0, s_d>>>(edges);
    scan_kernel<<<1, 8, 0, s_d>>>();
    fill_kernel<<<(BATCH * EE) / 256, 256, 0, s_d>>>(edges);
    cudaEventRecord(ev_d, s_d);

    // MLP1 fused, A gathered from entity_table -> S fp32
    {
        dim3 grid(1024 / 128, 4096 / 128, BATCH);
        gemm_fp<1><<<grid, 512, GSMEM>>>(nullptr, 0, entity_table, nodes + 4096, 8192,
                                         pWh + OFF_W1, pS, 512LL * 1024,
                                         4096, 1024, 768, mlp_b1, nullptr, 0,
                                         nullptr, nullptr, 0, 0, node_mask);
    }
    // join B (tpv', msum, Wnp, W2np, b2np, text vec)
    cudaStreamWaitEvent(0, ev_b, 0);
    // logic rows: h[513..1024] = S @ W2np + b2np*msum + tpv'[type]
    launch_g(pS, 512LL * 1024, nullptr, nullptr, 0, pWh + OFF_W2NP,
             pH + 513 * 256, 1025LL * 256, 512, 256, 1024,
             pB2np, pMsum + 512, 1024, pTpv, node_types + 513, 1025, 0);
    // text row h[0]
    h0_kernel<<<8, 256>>>(proj_w, node_types);
    // join C (pooled kg-half)
    cudaStreamWaitEvent(0, ev_c, 0);
    // kg rows: h[1..512] = pooled_kg @ Wnp + tpv'[type]
    launch_g(pPool, 1024LL * 768, nullptr, nullptr, 0, pWh + OFF_WNP,
             pH + 256, 1025LL * 256, 512, 256, 768,
             nullptr, nullptr, 0, pTpv, node_types + 1, 1025, 0);
    // join D (CSR) before GNN
    cudaStreamWaitEvent(0, ev_d, 0);
    // GNN layers: fused qkv gemm (Nc=768) then edge kernel
    for (int l = 0; l < 2; l++) {
        launch_g(pH, 1025LL * 256, nullptr, nullptr, 0,
                 pWh + OFF_QKV + l * 196608,
                 pQKV, 1025LL * 768, 1025, 768, 256,
                 nullptr, nullptr, 0, nullptr, nullptr, 0, 0);
        gnn_edge_kernel<<<dim3(1025, 8), 256>>>(pQKV, pH, edges, edge_types,
                                                pET + l * 50 * 256);
    }
    out_kernel<<<dim3(50, 8), 256>>>(out);
}